// round 5
// baseline (speedup 1.0000x reference)
#include <cuda_runtime.h>

// Problem constants (fixed by setup_inputs)
#define B_ 16
#define T_ 8192
#define D_ 64
#define D2 (D_ / 2)        // 32 float2 columns
#define CHUNK 16           // == WINDOW
#define YDIM 4
#define BLOCK_T (2 * CHUNK * YDIM) // 128 timesteps per block (32 per thread)

__device__ __forceinline__ float fexp2(float x) {
    float y; asm("ex2.approx.ftz.f32 %0, %1;" : "=f"(y) : "f"(x)); return y;
}
__device__ __forceinline__ float flog2(float x) {
    float y; asm("lg2.approx.ftz.f32 %0, %1;" : "=f"(y) : "f"(x)); return y;
}

// out[b,t,d] = -(1/5) * log( sum_{k=0..15} exp(-5 * x[b, max(t-k,0), d]) )
// Chunked prefix/suffix decomposition, float2 over D.
// Straight-line software pipeline: ALL 47 LDG.64 for the segment (15-step
// halo + two 16-step chunks) are issued back-to-back up front, so every
// warp keeps a deep memory queue in flight while the MUFU/FMA work runs.
// R4 showed DRAM stuck at 62% due to load/compute phase alternation.
__global__ __launch_bounds__(128) void always_kernel(
    const float* __restrict__ lower,
    const float* __restrict__ upper,
    float* __restrict__ out)
{
    const float C1 = -7.2134752044448169f;   // -5 * log2(e)
    const float C2 = -0.13862943611198906f;  // -ln(2) / 5

    const int d2 = threadIdx.x;              // 0..31 float2 column (coalesced)
    const int b  = blockIdx.y;               // 0..15
    const int tr = blockIdx.z;               // 0: lower, 1: upper
    const int t0 = blockIdx.x * BLOCK_T + threadIdx.y * (2 * CHUNK);

    const float* src = tr ? upper : lower;
    float*       dst = out + (size_t)tr * ((size_t)B_ * T_ * D_);

    const float2* col  = (const float2*)src + (size_t)b * T_ * D2 + d2;
    float2*       ocol = (float2*)dst      + (size_t)b * T_ * D2 + d2;

    // ---- Front-load ALL segment loads (47 independent LDG.64) ----
    // Halo: 15 preceding (index-clamped) timesteps. The clamp to index 0
    // reproduces h0's replication of x[:,0,:] exactly (duplicates ARE
    // counted in the logsumexp, matching the reference).
    float2 vh[16], v0[16], v1[16];
    #pragma unroll
    for (int k = 1; k < 16; k++) {
        int t = t0 - 16 + k;
        if (t < 0) t = 0;
        vh[k] = col[t * D2];
    }
    #pragma unroll
    for (int r = 0; r < 16; r++) v0[r] = col[(t0 + r) * D2];
    #pragma unroll
    for (int r = 0; r < 16; r++) v1[r] = col[(t0 + CHUNK + r) * D2];

    // ---- Halo suffix sums: sfx/sfy[k] = sum_{j>=k} exp(-5*x[t0-16+j]) ----
    float sfx[16], sfy[16];
    #pragma unroll
    for (int k = 1; k < 16; k++) {
        sfx[k] = fexp2(vh[k].x * C1);
        sfy[k] = fexp2(vh[k].y * C1);
    }
    #pragma unroll
    for (int k = 14; k >= 1; k--) { sfx[k] += sfx[k + 1]; sfy[k] += sfy[k + 1]; }

    // ---- Chunk 0 ----
    float ex[16], ey[16];
    #pragma unroll
    for (int r = 0; r < 16; r++) {
        ex[r] = fexp2(v0[r].x * C1);
        ey[r] = fexp2(v0[r].y * C1);
    }
    {
        float px = 0.0f, py = 0.0f;
        #pragma unroll
        for (int r = 0; r < 16; r++) {
            px += ex[r];
            py += ey[r];
            float wx = (r < 15) ? (px + sfx[r + 1]) : px;
            float wy = (r < 15) ? (py + sfy[r + 1]) : py;
            float2 o;
            o.x = flog2(wx) * C2;
            o.y = flog2(wy) * C2;
            ocol[(t0 + r) * D2] = o;
        }
    }
    // Rebuild suffix sums from chunk 0 for chunk 1's windows.
    #pragma unroll
    for (int k = 1; k < 16; k++) { sfx[k] = ex[k]; sfy[k] = ey[k]; }
    #pragma unroll
    for (int k = 14; k >= 1; k--) { sfx[k] += sfx[k + 1]; sfy[k] += sfy[k + 1]; }

    // ---- Chunk 1 ----
    #pragma unroll
    for (int r = 0; r < 16; r++) {
        ex[r] = fexp2(v1[r].x * C1);
        ey[r] = fexp2(v1[r].y * C1);
    }
    {
        float px = 0.0f, py = 0.0f;
        #pragma unroll
        for (int r = 0; r < 16; r++) {
            px += ex[r];
            py += ey[r];
            float wx = (r < 15) ? (px + sfx[r + 1]) : px;
            float wy = (r < 15) ? (py + sfy[r + 1]) : py;
            float2 o;
            o.x = flog2(wx) * C2;
            o.y = flog2(wy) * C2;
            ocol[(t0 + CHUNK + r) * D2] = o;
        }
    }
}

extern "C" void kernel_launch(void* const* d_in, const int* in_sizes, int n_in,
                              void* d_out, int out_size) {
    const float* lower = (const float*)d_in[0];
    const float* upper = (const float*)d_in[1];
    float* out = (float*)d_out;

    dim3 block(D2, YDIM);                  // 32 x 4 = 128 threads
    dim3 grid(T_ / BLOCK_T, B_, 2);        // 64 x 16 x 2 = 2048 blocks
    always_kernel<<<grid, block>>>(lower, upper, out);
}

// round 6
// speedup vs baseline: 1.1964x; 1.1964x over previous
#include <cuda_runtime.h>

// Problem constants (fixed by setup_inputs)
#define B_ 16
#define T_ 8192
#define D_ 64
#define D2 (D_ / 2)       // 32 float2 columns
#define CHUNK 16          // == WINDOW
#define CPT 4             // chunks per thread -> 64 timesteps per thread
#define TPT (CHUNK * CPT) // 64
#define YDIM 4
#define BLOCK_T (TPT * YDIM) // 256 timesteps per block

__device__ __forceinline__ float fexp2(float x) {
    float y; asm("ex2.approx.ftz.f32 %0, %1;" : "=f"(y) : "f"(x)); return y;
}
__device__ __forceinline__ float flog2(float x) {
    float y; asm("lg2.approx.ftz.f32 %0, %1;" : "=f"(y) : "f"(x)); return y;
}

// out[b,t,d] = -(1/5) * log( sum_{k=0..15} exp(-5 * x[b, max(t-k,0), d]) )
// R4 structure (best so far: 23.3us) + streaming stores: outputs are never
// re-read, so evict-first stores keep L2 capacity/bandwidth for the input
// lines (halo re-reads), raising DRAM duty cycle.
__global__ __launch_bounds__(128, 8) void always_kernel(
    const float* __restrict__ lower,
    const float* __restrict__ upper,
    float* __restrict__ out)
{
    const float C1 = -7.2134752044448169f;   // -5 * log2(e)
    const float C2 = -0.13862943611198906f;  // -ln(2) / 5

    const int d2 = threadIdx.x;              // 0..31 float2 column (coalesced)
    const int b  = blockIdx.y;               // 0..15
    const int tr = blockIdx.z;               // 0: lower, 1: upper
    const int t0 = blockIdx.x * BLOCK_T + threadIdx.y * TPT;

    const float* src = tr ? upper : lower;
    float*       dst = out + (size_t)tr * ((size_t)B_ * T_ * D_);

    const float2* col  = (const float2*)src + (size_t)b * T_ * D2 + d2;
    float2*       ocol = (float2*)dst      + (size_t)b * T_ * D2 + d2;

    // Suffix sums of the 15 preceding (index-clamped) timesteps.
    // Index clamp to 0 reproduces h0's replication of x[:,0,:] exactly
    // (duplicates ARE counted in the logsumexp, matching the reference).
    float sfx[16], sfy[16];
    {
        float ex[16], ey[16];
        #pragma unroll
        for (int k = 1; k < 16; k++) {
            int t = t0 - 16 + k;
            if (t < 0) t = 0;
            float2 v = col[t * D2];
            ex[k] = fexp2(v.x * C1);
            ey[k] = fexp2(v.y * C1);
        }
        float rx = 0.0f, ry = 0.0f;
        #pragma unroll
        for (int k = 15; k >= 1; k--) {
            rx += ex[k]; sfx[k] = rx;
            ry += ey[k]; sfy[k] = ry;
        }
    }

    int tc = t0;
    #pragma unroll 1
    for (int c = 0; c < CPT; c++) {
        // 16 independent LDG.64 -> high MLP, 256B per warp per slot.
        float ex[16], ey[16];
        #pragma unroll
        for (int r = 0; r < 16; r++) {
            float2 v = col[(tc + r) * D2];
            ex[r] = fexp2(v.x * C1);
            ey[r] = fexp2(v.y * C1);
        }

        // window_sum = prefix_cur[r] + suffix_prev[r+1] (exact 16-term sum).
        float px = 0.0f, py = 0.0f;
        #pragma unroll
        for (int r = 0; r < 16; r++) {
            px += ex[r];
            py += ey[r];
            float wx = (r < 15) ? (px + sfx[r + 1]) : px;
            float wy = (r < 15) ? (py + sfy[r + 1]) : py;
            float2 o;
            o.x = flog2(wx) * C2;
            o.y = flog2(wy) * C2;
            __stcs(&ocol[(tc + r) * D2], o);   // streaming store: evict-first in L2
        }

        // This chunk's suffix sums become "previous" for the next iteration.
        float rx = 0.0f, ry = 0.0f;
        #pragma unroll
        for (int k = 15; k >= 1; k--) {
            rx += ex[k]; sfx[k] = rx;
            ry += ey[k]; sfy[k] = ry;
        }

        tc += CHUNK;
    }
}

extern "C" void kernel_launch(void* const* d_in, const int* in_sizes, int n_in,
                              void* d_out, int out_size) {
    const float* lower = (const float*)d_in[0];
    const float* upper = (const float*)d_in[1];
    float* out = (float*)d_out;

    dim3 block(D2, YDIM);                  // 32 x 4 = 128 threads
    dim3 grid(T_ / BLOCK_T, B_, 2);        // 32 x 16 x 2 = 1024 blocks
    always_kernel<<<grid, block>>>(lower, upper, out);
}